// round 1
// baseline (speedup 1.0000x reference)
#include <cuda_runtime.h>
#include <cstdint>

// Problem constants (fixed for this problem instance)
#define BB   64    // batch
#define MH   64    // max_h
#define MW   32    // max_w
#define DD   512   // D
#define SS   8     // S (canonical grid)
#define HIDN 64    // HID

typedef unsigned long long ull;

// Precomputed gelu hidden activations, layout [b][y][k][x]  (33.5 MB scratch)
__device__ float g_h[(size_t)BB * MH * HIDN * MW];

// ---------------- f32x2 packed-FMA helpers (Blackwell FFMA2) ----------------
__device__ __forceinline__ ull dup2(float x) {
    ull r;
    asm("mov.b64 %0, {%1, %1};" : "=l"(r) : "f"(x));
    return r;
}
__device__ __forceinline__ void fma2(ull &acc, ull a, ull b) {
    asm("fma.rn.f32x2 %0, %1, %2, %0;" : "+l"(acc) : "l"(a), "l"(b));
}
__device__ __forceinline__ float2 unpack2(ull v) {
    float2 f;
    asm("mov.b64 {%0, %1}, %2;" : "=f"(f.x), "=f"(f.y) : "l"(v));
    return f;
}

// ---------------- Kernel 1: precompute h = gelu(coords @ w1 + b1) ----------
// grid (MH, BB), block HIDN threads (one per hidden unit)
__global__ void k_hidden(const float* __restrict__ w1, const float* __restrict__ b1,
                         const int* __restrict__ hl, const int* __restrict__ wl)
{
    int y = blockIdx.x, b = blockIdx.y, k = threadIdx.x;
    int Hs = min(max(hl[b], 1), MH);
    int Ws = min(max(wl[b], 1), MW);
    float u = (Hs > 1) ? (float)y / (float)(Hs - 1) : 0.f;
    float w1a = w1[k];          // w1[0][k]
    float w1b = w1[HIDN + k];   // w1[1][k]
    float b1k = b1[k];
    float base = fmaf(u, w1a, b1k);
    float invW = (Ws > 1) ? 1.f / (float)(Ws - 1) : 0.f;  // Ws==1 -> v = 0
    float* o = &g_h[((size_t)(b * MH + y) * HIDN + k) * MW];
    #pragma unroll
    for (int x = 0; x < MW; x++) {
        float v = (float)x * invW;
        float pre = fmaf(v, w1b, base);
        // exact gelu: x * 0.5 * (1 + erf(x/sqrt(2)))
        float h = 0.5f * pre * (1.f + erff(pre * 0.70710678118654752f));
        o[x] = h;
    }
}

// ---------------- Kernel 2: fused bilinear + delta GEMM + mask -------------
// grid (DD/128, MH, BB), block 256 threads
// Tile: M=32 (x), N=128 (d), K=64. Thread tile 4x * 4d, FMA over f32x2 pairs (d-dim).
__global__ void __launch_bounds__(256)
k_main(const float* __restrict__ canon, const float* __restrict__ w2,
       const float* __restrict__ b2, const int* __restrict__ hl,
       const int* __restrict__ wl, float* __restrict__ out)
{
    __shared__ __align__(16) float smem[11264];           // 44 KB
    float* w2_s = smem;                                   // 64*128 floats (32 KB)
    ull*   hd_s = (ull*)(smem + 8192);                    // 32*32 ulls   (8 KB)
    float* cy_s = smem + 8192 + 2048;                     // 8*128 floats (4 KB)

    const int dt = blockIdx.x, y = blockIdx.y, b = blockIdx.z;
    const int d0 = dt * 128;
    const int tid = threadIdx.x;

    // --- load w2 tile [64][128] ---
    #pragma unroll
    for (int i = 0; i < 8; i++) {
        int lin = tid + i * 256;            // 2048 float4 groups
        int kk = lin >> 5;
        int jj = (lin & 31) << 2;
        *(float4*)&w2_s[kk * 128 + jj] = *(const float4*)&w2[kk * DD + d0 + jj];
    }

    const int Hs = min(max(hl[b], 1), MH);
    const int Ws = min(max(wl[b], 1), MW);
    const float u  = (Hs > 1) ? (float)y / (float)(Hs - 1) : 0.f;
    float sy = fminf(fmaxf(u * (float)(SS - 1), 0.f), (float)(SS - 1));
    int   y0 = (int)floorf(sy);
    int   y1 = min(y0 + 1, SS - 1);
    float wy = sy - (float)y0;

    // --- cy tile: y-lerped canonical rows, 8 x-cols * 128 d (1 float4/thread) ---
    {
        int xx = tid >> 5;
        int jj = (tid & 31) << 2;
        float4 c0 = *(const float4*)&canon[(y0 * SS + xx) * DD + d0 + jj];
        float4 c1 = *(const float4*)&canon[(y1 * SS + xx) * DD + d0 + jj];
        float4 r;
        r.x = c0.x + wy * (c1.x - c0.x);
        r.y = c0.y + wy * (c1.y - c0.y);
        r.z = c0.z + wy * (c1.z - c0.z);
        r.w = c0.w + wy * (c1.w - c0.w);
        *(float4*)&cy_s[xx * 128 + jj] = r;
    }

    const int tn = tid & 31;       // d group: d = d0 + tn*4
    const int tm = tid >> 5;       // x group: x = tm*4 .. tm*4+3

    ull acc[4][2];
    #pragma unroll
    for (int i = 0; i < 4; i++) { acc[i][0] = 0ULL; acc[i][1] = 0ULL; }

    const float* gh = &g_h[(size_t)(b * MH + y) * HIDN * MW];

    // --- GEMM mainloop, K split into 2 chunks of 32 ---
    for (int kc = 0; kc < HIDN; kc += 32) {
        __syncthreads();   // covers w2/cy fill on first pass; hd_s reuse after
        {   // fill duplicated h tile: 1024 ulls, 4 per thread
            float4 hv = *(const float4*)&gh[kc * MW + tid * 4];
            hd_s[tid * 4 + 0] = dup2(hv.x);
            hd_s[tid * 4 + 1] = dup2(hv.y);
            hd_s[tid * 4 + 2] = dup2(hv.z);
            hd_s[tid * 4 + 3] = dup2(hv.w);
        }
        __syncthreads();
        #pragma unroll
        for (int k = 0; k < 32; k++) {
            ulonglong2 a01 = *(const ulonglong2*)&hd_s[k * 32 + tm * 4];
            ulonglong2 a23 = *(const ulonglong2*)&hd_s[k * 32 + tm * 4 + 2];
            ulonglong2 bv  = *(const ulonglong2*)&w2_s[(kc + k) * 128 + tn * 4];
            fma2(acc[0][0], a01.x, bv.x); fma2(acc[0][1], a01.x, bv.y);
            fma2(acc[1][0], a01.y, bv.x); fma2(acc[1][1], a01.y, bv.y);
            fma2(acc[2][0], a23.x, bv.x); fma2(acc[2][1], a23.x, bv.y);
            fma2(acc[3][0], a23.y, bv.x); fma2(acc[3][1], a23.y, bv.y);
        }
    }

    // --- epilogue: + b2 + bilinear, apply mask, vectorized store ---
    const float invW = (Ws > 1) ? 1.f / (float)(Ws - 1) : 0.f;
    const float4 b2v = *(const float4*)&b2[d0 + tn * 4];
    #pragma unroll
    for (int xi = 0; xi < 4; xi++) {
        int x = tm * 4 + xi;
        float v  = (float)x * invW;
        float sx = fminf(fmaxf(v * (float)(SS - 1), 0.f), (float)(SS - 1));
        int   x0 = (int)floorf(sx);
        int   x1 = min(x0 + 1, SS - 1);
        float wx = sx - (float)x0;
        float4 c0 = *(const float4*)&cy_s[x0 * 128 + tn * 4];
        float4 c1 = *(const float4*)&cy_s[x1 * 128 + tn * 4];
        bool m = (y < Hs) && (x < Ws);
        float2 p0 = unpack2(acc[xi][0]);
        float2 p1 = unpack2(acc[xi][1]);
        float4 o;
        o.x = m ? (p0.x + b2v.x + c0.x + wx * (c1.x - c0.x)) : 0.f;
        o.y = m ? (p0.y + b2v.y + c0.y + wx * (c1.y - c0.y)) : 0.f;
        o.z = m ? (p1.x + b2v.z + c0.z + wx * (c1.z - c0.z)) : 0.f;
        o.w = m ? (p1.y + b2v.w + c0.w + wx * (c1.w - c0.w)) : 0.f;
        *(float4*)&out[((size_t)(b * MH + y) * MW + x) * DD + d0 + tn * 4] = o;
    }
}

// ---------------- Kernel 3: mask output (if present) -----------------------
__global__ void k_mask(const int* __restrict__ hl, const int* __restrict__ wl,
                       float* __restrict__ out)
{
    int i = blockIdx.x * 256 + threadIdx.x;     // < BB*MH*MW
    int x = i & (MW - 1);
    int y = (i >> 5) & (MH - 1);
    int b = i >> 11;
    int Hs = min(max(hl[b], 1), MH);
    int Ws = min(max(wl[b], 1), MW);
    out[(size_t)BB * MH * MW * DD + i] = ((y < Hs) && (x < Ws)) ? 1.f : 0.f;
}

extern "C" void kernel_launch(void* const* d_in, const int* in_sizes, int n_in,
                              void* d_out, int out_size)
{
    const float* canon = (const float*)d_in[0];   // [8][8][512]
    const float* w1    = (const float*)d_in[1];   // [2][64]
    const float* b1    = (const float*)d_in[2];   // [64]
    const float* w2    = (const float*)d_in[3];   // [64][512]
    const float* b2    = (const float*)d_in[4];   // [512]
    // d_in[5] = batch_size (device scalar, unused; B fixed)
    const int* hl = (const int*)d_in[6];          // target_h_list [64]
    const int* wl = (const int*)d_in[7];          // target_w_list [64]
    // d_in[8], d_in[9] = max_h, max_w (device scalars, fixed)
    float* out = (float*)d_out;

    k_hidden<<<dim3(MH, BB), HIDN>>>(w1, b1, hl, wl);
    k_main<<<dim3(DD / 128, MH, BB), 256>>>(canon, w2, b2, hl, wl, out);

    long long q = (long long)BB * MH * MW * DD;
    if ((long long)out_size > q) {
        k_mask<<<(BB * MH * MW) / 256, 256>>>(hl, wl, out);
    }
}

// round 2
// speedup vs baseline: 2.5200x; 2.5200x over previous
#include <cuda_runtime.h>
#include <cstdint>

#define BB   64
#define MH   64
#define MW   32
#define DD   512
#define SS   8
#define HIDN 64

typedef unsigned long long ull;

// ---------------- f32x2 packed helpers (Blackwell FFMA2 via PTX) -----------
__device__ __forceinline__ ull dup2(float x) {
    ull r; asm("mov.b64 %0, {%1, %1};" : "=l"(r) : "f"(x)); return r;
}
__device__ __forceinline__ void fma2(ull &a, ull x, ull y) {
    asm("fma.rn.f32x2 %0, %1, %2, %0;" : "+l"(a) : "l"(x), "l"(y));
}
__device__ __forceinline__ float2 unpack2(ull v) {
    float2 f; asm("mov.b64 {%0, %1}, %2;" : "=f"(f.x), "=f"(f.y) : "l"(v)); return f;
}

// ---------------------------------------------------------------------------
// Fused kernel: block = (b, y-pair). For each valid row:
//   h = gelu(coords @ w1 + b1) computed in-block into smem,
//   delta = h @ w2 (M=32 x, N=512 d, K=64) with 8x*8d thread tiles (f32x2),
//   out = mask ? bilinear(canonical) + delta + b2 : 0
// Invalid rows: pure zero-store. Warps whose x-chunk >= Ws skip the GEMM.
// Smem: w2 [64][512] 128KB + h [64][32] 8KB + cy [8][512] 16KB = 152KB.
// ---------------------------------------------------------------------------
__global__ void __launch_bounds__(256, 1)
k_main(const float* __restrict__ canon, const float* __restrict__ w1,
       const float* __restrict__ b1, const float* __restrict__ w2g,
       const float* __restrict__ b2, const int* __restrict__ hl,
       const int* __restrict__ wl, float* __restrict__ out)
{
    extern __shared__ float smem[];
    float* w2_s = smem;                 // 32768 floats
    float* a_s  = smem + 32768;         // 2048 floats: h[k][x]
    float* cy_s = smem + 34816;         // 4096 floats: lerped canon [8][512]

    const int b = blockIdx.y;
    const int ybase = blockIdx.x * 2;
    const int tid = threadIdx.x;

    const int Hs = min(max(hl[b], 1), MH);
    const int Ws = min(max(wl[b], 1), MW);
    const float invH = (Hs > 1) ? 1.f / (float)(Hs - 1) : 0.f;
    const float invW = (Ws > 1) ? 1.f / (float)(Ws - 1) : 0.f;

    // Both rows invalid -> pure zero-store (memory-bound fast path)
    if (ybase >= Hs) {
        float4 z = make_float4(0.f, 0.f, 0.f, 0.f);
        float* o = out + (size_t)(b * MH + ybase) * MW * DD;
        #pragma unroll
        for (int i = 0; i < 32; i++)               // 2 rows * 4096 float4
            *(float4*)&o[(tid + i * 256) * 4] = z;
        return;
    }

    // ---- stage w2 [64][512] once per block (reused across both rows) ----
    #pragma unroll
    for (int i = 0; i < 32; i++) {
        int lin = (tid + i * 256) * 4;
        *(float4*)&w2_s[lin] = *(const float4*)&w2g[lin];
    }

    const int tn  = tid & 63;          // d group: d = tn*8 .. tn*8+7
    const int tm  = tid >> 6;          // warp-uniform x group (warps w,w+1 share tm)
    const int x0b = tm * 8;

    // gelu fill assignment: lane dim = x (conflict-free STS), 8 k's per thread
    const int gx  = tid & 31;
    const int gk0 = (tid >> 5) * 8;
    const float gv = (float)gx * invW;

    const float4 b2a = *(const float4*)&b2[tn * 8];
    const float4 b2b = *(const float4*)&b2[tn * 8 + 4];

    for (int ry = 0; ry < 2; ry++) {
        const int y = ybase + ry;
        float* orow = out + (size_t)(b * MH + y) * MW * DD;

        if (y >= Hs) {   // row invalid (block-uniform): zero-store
            float4 z = make_float4(0.f, 0.f, 0.f, 0.f);
            #pragma unroll
            for (int i = 0; i < 16; i++)
                *(float4*)&orow[(tid + i * 256) * 4] = z;
            continue;
        }

        const float u = (float)y * invH;

        __syncthreads();   // prior-row readers done (also harmless on ry==0)

        // ---- h = gelu(u*w1a + v*w1b + b1) into a_s[k][x] ----
        #pragma unroll
        for (int j = 0; j < 8; j++) {
            int k = gk0 + j;
            float pre = fmaf(u, w1[k], fmaf(gv, w1[HIDN + k], b1[k]));
            a_s[k * MW + gx] =
                0.5f * pre * (1.f + erff(pre * 0.70710678118654752f));
        }

        // ---- cy: y-lerped canonical rows [8][512] ----
        {
            float sy = fminf(u * (float)(SS - 1), (float)(SS - 1));
            int   yy0 = (int)sy;
            int   yy1 = min(yy0 + 1, SS - 1);
            float wy = sy - (float)yy0;
            #pragma unroll
            for (int i = 0; i < 4; i++) {
                int lin = tid + i * 256;            // 1024 float4
                int xx  = lin >> 7;
                int off = (lin & 127) * 4;
                float4 c0 = *(const float4*)&canon[(yy0 * SS + xx) * DD + off];
                float4 c1 = *(const float4*)&canon[(yy1 * SS + xx) * DD + off];
                float4 r;
                r.x = fmaf(wy, c1.x - c0.x, c0.x);
                r.y = fmaf(wy, c1.y - c0.y, c0.y);
                r.z = fmaf(wy, c1.z - c0.z, c0.z);
                r.w = fmaf(wy, c1.w - c0.w, c0.w);
                *(float4*)&cy_s[xx * DD + off] = r;
            }
        }
        __syncthreads();

        // ---- GEMM mainloop: acc[8 x][8 d] per thread, f32x2 pairs over d ----
        ull acc[8][4];
        #pragma unroll
        for (int m = 0; m < 8; m++)
            #pragma unroll
            for (int p = 0; p < 4; p++) acc[m][p] = 0ULL;

        if (x0b < Ws) {      // warp-uniform skip of fully-masked x-chunks
            #pragma unroll 4
            for (int k = 0; k < HIDN; k++) {
                float4 a0 = *(float4*)&a_s[k * MW + x0b];       // broadcast
                float4 a1 = *(float4*)&a_s[k * MW + x0b + 4];   // broadcast
                ull ad[8];
                ad[0] = dup2(a0.x); ad[1] = dup2(a0.y);
                ad[2] = dup2(a0.z); ad[3] = dup2(a0.w);
                ad[4] = dup2(a1.x); ad[5] = dup2(a1.y);
                ad[6] = dup2(a1.z); ad[7] = dup2(a1.w);
                ulonglong2 b01 = *(ulonglong2*)&w2_s[k * DD + tn * 8];
                ulonglong2 b23 = *(ulonglong2*)&w2_s[k * DD + tn * 8 + 4];
                #pragma unroll
                for (int m = 0; m < 8; m++) {
                    fma2(acc[m][0], ad[m], b01.x);
                    fma2(acc[m][1], ad[m], b01.y);
                    fma2(acc[m][2], ad[m], b23.x);
                    fma2(acc[m][3], ad[m], b23.y);
                }
            }
        }

        // ---- epilogue: + b2 + bilinear-x, mask, vectorized store ----
        #pragma unroll
        for (int m = 0; m < 8; m++) {
            int x = x0b + m;
            float4 oa = make_float4(0.f, 0.f, 0.f, 0.f);
            float4 ob = make_float4(0.f, 0.f, 0.f, 0.f);
            if (x < Ws) {
                float sx = fminf((float)x * invW * (float)(SS - 1),
                                 (float)(SS - 1));
                int   xx0 = (int)sx;
                int   xx1 = min(xx0 + 1, SS - 1);
                float wx = sx - (float)xx0;
                float4 ca0 = *(float4*)&cy_s[xx0 * DD + tn * 8];
                float4 ca1 = *(float4*)&cy_s[xx1 * DD + tn * 8];
                float4 cb0 = *(float4*)&cy_s[xx0 * DD + tn * 8 + 4];
                float4 cb1 = *(float4*)&cy_s[xx1 * DD + tn * 8 + 4];
                float2 p0 = unpack2(acc[m][0]);
                float2 p1 = unpack2(acc[m][1]);
                float2 p2 = unpack2(acc[m][2]);
                float2 p3 = unpack2(acc[m][3]);
                oa.x = p0.x + b2a.x + fmaf(wx, ca1.x - ca0.x, ca0.x);
                oa.y = p0.y + b2a.y + fmaf(wx, ca1.y - ca0.y, ca0.y);
                oa.z = p1.x + b2a.z + fmaf(wx, ca1.z - ca0.z, ca0.z);
                oa.w = p1.y + b2a.w + fmaf(wx, ca1.w - ca0.w, ca0.w);
                ob.x = p2.x + b2b.x + fmaf(wx, cb1.x - cb0.x, cb0.x);
                ob.y = p2.y + b2b.y + fmaf(wx, cb1.y - cb0.y, cb0.y);
                ob.z = p3.x + b2b.z + fmaf(wx, cb1.z - cb0.z, cb0.z);
                ob.w = p3.y + b2b.w + fmaf(wx, cb1.w - cb0.w, cb0.w);
            }
            *(float4*)&orow[x * DD + tn * 8]     = oa;
            *(float4*)&orow[x * DD + tn * 8 + 4] = ob;
        }
    }
}

// ---------------- mask output (if the harness output includes it) ----------
__global__ void k_mask(const int* __restrict__ hl, const int* __restrict__ wl,
                       float* __restrict__ out)
{
    int i = blockIdx.x * 256 + threadIdx.x;     // < BB*MH*MW
    int x = i & (MW - 1);
    int y = (i >> 5) & (MH - 1);
    int b = i >> 11;
    int Hs = min(max(hl[b], 1), MH);
    int Ws = min(max(wl[b], 1), MW);
    out[(size_t)BB * MH * MW * DD + i] = ((y < Hs) && (x < Ws)) ? 1.f : 0.f;
}

extern "C" void kernel_launch(void* const* d_in, const int* in_sizes, int n_in,
                              void* d_out, int out_size)
{
    const float* canon = (const float*)d_in[0];   // [8][8][512]
    const float* w1    = (const float*)d_in[1];   // [2][64]
    const float* b1    = (const float*)d_in[2];   // [64]
    const float* w2    = (const float*)d_in[3];   // [64][512]
    const float* b2    = (const float*)d_in[4];   // [512]
    const int*   hl    = (const int*)d_in[6];     // target_h_list [64]
    const int*   wl    = (const int*)d_in[7];     // target_w_list [64]
    float* out = (float*)d_out;

    static const int SMEM_BYTES = 38912 * 4;      // 152 KB dynamic smem
    cudaFuncSetAttribute(k_main, cudaFuncAttributeMaxDynamicSharedMemorySize,
                         SMEM_BYTES);

    k_main<<<dim3(MH / 2, BB), 256, SMEM_BYTES>>>(canon, w1, b1, w2, b2,
                                                  hl, wl, out);

    long long q = (long long)BB * MH * MW * DD;
    if ((long long)out_size > q) {
        k_mask<<<(BB * MH * MW) / 256, 256>>>(hl, wl, out);
    }
}